// round 12
// baseline (speedup 1.0000x reference)
#include <cuda_runtime.h>
#include <cuda_fp16.h>
#include <cstdint>

#define E_  8
#define T_  2048
#define H_  2880
#define D_  2880
#define N2_ 5760

__device__ __half g_xh[(size_t)T_ * H_];
__device__ __half g_w1t[(size_t)E_ * N2_ * H_];
__device__ __half g_w2t[(size_t)E_ * H_ * D_];
__device__ __half g_hidden[(size_t)E_ * T_ * D_];

// ---------------- helpers ----------------
__device__ __forceinline__ unsigned smem_u32(const void* p) {
    return (unsigned)__cvta_generic_to_shared(p);
}
__device__ __forceinline__ void cp16h(__half* s, const __half* g) {
    asm volatile("cp.async.cg.shared.global [%0], [%1], 16;" :: "r"(smem_u32(s)), "l"(g));
}
__device__ __forceinline__ void cp_commit() { asm volatile("cp.async.commit_group;"); }
__device__ __forceinline__ void cp_wait1()  { asm volatile("cp.async.wait_group 1;"); }
__device__ __forceinline__ void cp_wait0()  { asm volatile("cp.async.wait_group 0;"); }

__device__ __forceinline__ void mma16(float* c, const uint32_t* a, const uint32_t* b) {
    asm volatile("mma.sync.aligned.m16n8k16.row.col.f32.f16.f16.f32 "
        "{%0,%1,%2,%3}, {%4,%5,%6,%7}, {%8,%9}, {%0,%1,%2,%3};"
        : "+f"(c[0]), "+f"(c[1]), "+f"(c[2]), "+f"(c[3])
        : "r"(a[0]), "r"(a[1]), "r"(a[2]), "r"(a[3]), "r"(b[0]), "r"(b[1]));
}
__device__ __forceinline__ void ldsm4(uint32_t& r0, uint32_t& r1, uint32_t& r2, uint32_t& r3,
                                      uint32_t addr) {
    asm volatile("ldmatrix.sync.aligned.m8n8.x4.shared.b16 {%0,%1,%2,%3}, [%4];"
        : "=r"(r0), "=r"(r1), "=r"(r2), "=r"(r3) : "r"(addr));
}
__device__ __forceinline__ void ldsm2(uint32_t& r0, uint32_t& r1, uint32_t addr) {
    asm volatile("ldmatrix.sync.aligned.m8n8.x2.shared.b16 {%0,%1}, [%2];"
        : "=r"(r0), "=r"(r1) : "r"(addr));
}

// ---------------- tiling ----------------
constexpr int BM = 128, BN = 160, BK = 64;
constexpr int NT = 256;
constexpr int WN = 40, NF = 5;
constexpr int A_BYTES = BM * 128;
constexpr int B_BYTES = BN * 128;
constexpr int STG_B = A_BYTES + B_BYTES;       // 36864
constexpr int STAGES = 3;
constexpr int SMEM_B = STAGES * STG_B;         // 110592 -> 2 CTAs/SM

// one 16B chunk of a swizzled tile (A: chunks 0..3, B: chunks 0..4)
__device__ __forceinline__ void load_chunk(__half* S, const __half* G, int lda, int tid, int i) {
    int c = tid + i * NT;
    int r = c >> 3, q = c & 7;
    cp16h(S + r * 64 + ((q ^ (r & 7)) << 3), G + (size_t)r * lda + q * 8);
}
template<int ROWS>
__device__ __forceinline__ void load_tile(__half* S, const __half* G, int lda, int tid) {
#pragma unroll
    for (int i = 0; i < ROWS * 8 / NT; i++) load_chunk(S, G, lda, tid, i);
}

__device__ __forceinline__ void offs_A(uint32_t (&aOff)[4], int wm, int lane) {
    const int rr = lane & 7, mm = lane >> 3;
#pragma unroll
    for (int i = 0; i < 4; i++) {
        const int row = wm * 64 + i * 16 + (mm & 1) * 8 + rr;
        aOff[i] = row * 128 + ((((mm >> 1) ^ (row & 7)) & 7) << 4);
    }
}
__device__ __forceinline__ void offs_B(uint32_t (&bOff)[3], int wn, int lane) {
    const int rr = lane & 7, mm = lane >> 3;
#pragma unroll
    for (int jp = 0; jp < 2; jp++) {
        const int row = wn * WN + (jp * 2 + (mm >> 1)) * 8 + rr;
        bOff[jp] = row * 128 + ((((mm & 1) ^ (row & 7)) & 7) << 4);
    }
    {
        const int row = wn * WN + 32 + rr;
        bOff[2] = row * 128 + ((((mm & 1) ^ (row & 7)) & 7) << 4);
    }
}

__device__ __forceinline__ void ldsm_batch(uint32_t sA, uint32_t sB,
                                           const uint32_t (&aOff)[4],
                                           const uint32_t (&bOff)[3],
                                           int ks, uint32_t (&a)[4][4], uint32_t (&b)[NF][2]) {
    const uint32_t kx = ks * 32;
#pragma unroll
    for (int i = 0; i < 4; i++)
        ldsm4(a[i][0], a[i][1], a[i][2], a[i][3], sA + (aOff[i] ^ kx));
    ldsm4(b[0][0], b[0][1], b[1][0], b[1][1], sB + (bOff[0] ^ kx));
    ldsm4(b[2][0], b[2][1], b[3][0], b[3][1], sB + (bOff[1] ^ kx));
    ldsm2(b[4][0], b[4][1], sB + (bOff[2] ^ kx));
}
__device__ __forceinline__ void mma_batch(const uint32_t (&a)[4][4], const uint32_t (&b)[NF][2],
                                          float (&acc)[4][NF][4]) {
#pragma unroll
    for (int i = 0; i < 4; i++)
#pragma unroll
        for (int j = 0; j < NF; j++)
            mma16(acc[i][j], a[i], b[j]);
}

// ================= preprocess =================
__global__ void k_tohalf(const float2* __restrict__ in, __half2* __restrict__ out, size_t n2) {
    size_t i = (size_t)blockIdx.x * blockDim.x + threadIdx.x;
    size_t st = (size_t)gridDim.x * blockDim.x;
    for (; i < n2; i += st) {
        float2 v = in[i];
        out[i] = __floats2half2_rn(v.x, v.y);
    }
}
// [z][R][C] fp32 -> [z][C][R] fp16; 64-row x 32-col tiles, half2 coalesced stores
__global__ void k_transpose_h(const float* __restrict__ in, __half* __restrict__ out, int R, int C) {
    __shared__ float t[64][33];
    const float* iz = in + (size_t)blockIdx.z * R * C;
    __half* oz = out + (size_t)blockIdx.z * R * C;
    const int c0 = blockIdx.x * 32, r0 = blockIdx.y * 64;
    const int tx = threadIdx.x, ty = threadIdx.y;
#pragma unroll
    for (int i = 0; i < 64; i += 8)
        t[ty + i][tx] = iz[(size_t)(r0 + ty + i) * C + c0 + tx];
    __syncthreads();
#pragma unroll
    for (int j = 0; j < 4; j++) {
        const int cc = ty + 8 * j;
        __half2 v = __floats2half2_rn(t[2 * tx][cc], t[2 * tx + 1][cc]);
        *(__half2*)(oz + (size_t)(c0 + cc) * R + r0 + 2 * tx) = v;
    }
}

// ================= GEMM1 =================
__global__ void __launch_bounds__(NT, 2)
k_gemm1(const float* __restrict__ b1, const float* __restrict__ routing) {
    extern __shared__ __align__(128) char smc[];
    __half* smh = (__half*)smc;
    float* smf = (float*)smc;
    const int tid = threadIdx.x, lane = tid & 31, warp = tid >> 5;
    const int wm = warp & 1, wn = warp >> 1;
    const int n0 = blockIdx.x * BN;
    const int t0 = blockIdx.y * BM;
    const int e  = blockIdx.z;

    const uint32_t sb = smem_u32(smc);
    const __half* Ag = g_xh + (size_t)t0 * H_;
    const __half* Bg = g_w1t + ((size_t)e * N2_ + n0) * H_;

    uint32_t aOff[4], bOff[3];
    offs_A(aOff, wm, lane);
    offs_B(bOff, wn, lane);

    float acc[4][NF][4];
#pragma unroll
    for (int i = 0; i < 4; i++)
#pragma unroll
        for (int j = 0; j < NF; j++)
#pragma unroll
            for (int q = 0; q < 4; q++) acc[i][j][q] = 0.f;

    constexpr int KT = H_ / BK;   // 45
#pragma unroll
    for (int s = 0; s < 2; s++) {
        load_tile<BM>(smh + s * STG_B / 2, Ag + s * BK, H_, tid);
        load_tile<BN>(smh + (s * STG_B + A_BYTES) / 2, Bg + s * BK, H_, tid);
        cp_commit();
    }

    for (int kt = 0; kt < KT; kt++) {
        if (kt < KT - 1) cp_wait1(); else cp_wait0();
        __syncthreads();
        const int s = kt % 3;
        const uint32_t sA = sb + s * STG_B, sB = sA + A_BYTES;
        const int nk = kt + 2;
        const bool ld = nk < KT;
        __half* An = nullptr; __half* Bn = nullptr;
        const __half *Ga = nullptr, *Gb = nullptr;
        if (ld) {
            const int ns = nk % 3;
            An = smh + ns * STG_B / 2; Bn = An + A_BYTES / 2;
            Ga = Ag + nk * BK;         Gb = Bg + nk * BK;
        }
        uint32_t a[4][4], b[NF][2];
#pragma unroll
        for (int ks = 0; ks < 4; ks++) {
            ldsm_batch(sA, sB, aOff, bOff, ks, a, b);
            if (ld) {                               // spread cp.async across ks
                load_chunk(An, Ga, H_, tid, ks);
                load_chunk(Bn, Gb, H_, tid, ks);
                if (ks == 3) load_chunk(Bn, Gb, H_, tid, 4);
            }
            mma_batch(a, b, acc);
        }
        if (ld) cp_commit();
    }

    __syncthreads();
    if (tid < BN) smf[tid] = b1[(size_t)e * N2_ + n0 + tid];
    __syncthreads();

    const int ra = lane >> 2, ca2 = 2 * (lane & 3);
#pragma unroll
    for (int i = 0; i < 4; i++)
#pragma unroll
        for (int h = 0; h < 2; h++) {
            const int row = wm * 64 + i * 16 + h * 8 + ra;
            const float rw = routing[(size_t)(t0 + row) * E_ + e];
            __half* gh = g_hidden + ((size_t)e * T_ + t0 + row) * D_ + (n0 >> 1);
#pragma unroll
            for (int j = 0; j < NF; j++) {
                const int C = wn * WN + j * 8 + ca2;
                float gate = acc[i][j][2 * h]     + smf[C];
                float up   = acc[i][j][2 * h + 1] + smf[C + 1];
                gate = fminf(gate, 7.0f);
                up   = fminf(fmaxf(up, -7.0f), 7.0f);
                const float glu = gate / (1.0f + __expf(-1.702f * gate));
                gh[C >> 1] = __float2half_rn((up + 1.0f) * glu * rw);
            }
        }
}

// ================= GEMM2 =================
__global__ void __launch_bounds__(NT, 2)
k_gemm2(const float* __restrict__ b2, const float* __restrict__ routing,
        float* __restrict__ out) {
    extern __shared__ __align__(128) char smc[];
    __half* smh = (__half*)smc;
    float* smf = (float*)smc;
    const int tid = threadIdx.x, lane = tid & 31, warp = tid >> 5;
    const int wm = warp & 1, wn = warp >> 1;
    const int h0 = blockIdx.x * BN;
    const int t0 = blockIdx.y * BM;

    const uint32_t sb = smem_u32(smc);
    uint32_t aOff[4], bOff[3];
    offs_A(aOff, wm, lane);
    offs_B(bOff, wn, lane);

    float acc[4][NF][4];
#pragma unroll
    for (int i = 0; i < 4; i++)
#pragma unroll
        for (int j = 0; j < NF; j++)
#pragma unroll
            for (int q = 0; q < 4; q++) acc[i][j][q] = 0.f;

    constexpr int KPE = D_ / BK;   // 45
    constexpr int KT  = E_ * KPE;  // 360

#pragma unroll
    for (int s = 0; s < 2; s++) {
        load_tile<BM>(smh + s * STG_B / 2, g_hidden + (size_t)t0 * D_ + s * BK, D_, tid);
        load_tile<BN>(smh + (s * STG_B + A_BYTES) / 2, g_w2t + (size_t)h0 * D_ + s * BK, D_, tid);
        cp_commit();
    }

    int ez = 0, kk = 2;
    for (int kt = 0; kt < KT; kt++) {
        if (kt < KT - 1) cp_wait1(); else cp_wait0();
        __syncthreads();
        const int s = kt % 3;
        const uint32_t sA = sb + s * STG_B, sB = sA + A_BYTES;
        const int nk = kt + 2;
        const bool ld = nk < KT;
        __half* An = nullptr; __half* Bn = nullptr;
        const __half *Ga = nullptr, *Gb = nullptr;
        if (ld) {
            const int ns = nk % 3;
            An = smh + ns * STG_B / 2; Bn = An + A_BYTES / 2;
            Ga = g_hidden + ((size_t)ez * T_ + t0) * D_ + kk * BK;
            Gb = g_w2t + ((size_t)ez * H_ + h0) * D_ + kk * BK;
            if (++kk == KPE) { kk = 0; ez++; }
        }
        uint32_t a[4][4], b[NF][2];
#pragma unroll
        for (int ks = 0; ks < 4; ks++) {
            ldsm_batch(sA, sB, aOff, bOff, ks, a, b);
            if (ld) {
                load_chunk(An, Ga, D_, tid, ks);
                load_chunk(Bn, Gb, D_, tid, ks);
                if (ks == 3) load_chunk(Bn, Gb, D_, tid, 4);
            }
            mma_batch(a, b, acc);
        }
        if (ld) cp_commit();
    }

    __syncthreads();
    for (int i = tid; i < E_ * BN; i += NT) {
        const int ee = i / BN, c = i - ee * BN;
        smf[i] = b2[(size_t)ee * H_ + h0 + c];
    }
    __syncthreads();

    const int ra = lane >> 2, ca2 = 2 * (lane & 3);
#pragma unroll
    for (int i = 0; i < 4; i++)
#pragma unroll
        for (int h = 0; h < 2; h++) {
            const int t = t0 + wm * 64 + i * 16 + h * 8 + ra;
            const float4 r03 = ((const float4*)routing)[(size_t)t * 2];
            const float4 r47 = ((const float4*)routing)[(size_t)t * 2 + 1];
            const float rwv[8] = { r03.x, r03.y, r03.z, r03.w, r47.x, r47.y, r47.z, r47.w };
            float* orow = out + (size_t)t * H_ + h0;
#pragma unroll
            for (int j = 0; j < NF; j++) {
                const int C = wn * WN + j * 8 + ca2;
                float v0 = acc[i][j][2 * h];
                float v1 = acc[i][j][2 * h + 1];
#pragma unroll
                for (int ee = 0; ee < E_; ee++) {
                    v0 += rwv[ee] * smf[ee * BN + C];
                    v1 += rwv[ee] * smf[ee * BN + C + 1];
                }
                *(float2*)(orow + C) = make_float2(v0, v1);
            }
        }
}

// ================= host ====================
extern "C" void kernel_launch(void* const* d_in, const int* in_sizes, int n_in,
                              void* d_out, int out_size) {
    const float *x = nullptr, *rw = nullptr, *w1 = nullptr, *b1 = nullptr,
                *w2 = nullptr, *b2 = nullptr;
    for (int i = 0; i < n_in; i++) {
        const long long s = in_sizes[i];
        const float* p = (const float*)d_in[i];
        if      (s == (long long)T_ * H_)        x  = p;
        else if (s == (long long)T_ * E_)        rw = p;
        else if (s == (long long)E_ * H_ * N2_)  w1 = p;
        else if (s == (long long)E_ * N2_)       b1 = p;
        else if (s == (long long)E_ * D_ * H_)   w2 = p;
        else if (s == (long long)E_ * H_)        b2 = p;
    }
    float* out = (float*)d_out;

    void *p_xh, *p_w1t, *p_w2t;
    cudaGetSymbolAddress(&p_xh,  g_xh);
    cudaGetSymbolAddress(&p_w1t, g_w1t);
    cudaGetSymbolAddress(&p_w2t, g_w2t);

    cudaFuncSetAttribute(k_gemm1, cudaFuncAttributeMaxDynamicSharedMemorySize, SMEM_B);
    cudaFuncSetAttribute(k_gemm2, cudaFuncAttributeMaxDynamicSharedMemorySize, SMEM_B);

    k_tohalf<<<4096, 256>>>((const float2*)x, (__half2*)p_xh, (size_t)T_ * H_ / 2);
    dim3 tb(32, 8);
    k_transpose_h<<<dim3(N2_ / 32, H_ / 64, E_), tb>>>(w1, (__half*)p_w1t, H_, N2_);
    k_transpose_h<<<dim3(H_ / 32, D_ / 64, E_), tb>>>(w2, (__half*)p_w2t, D_, H_);

    k_gemm1<<<dim3(N2_ / BN, T_ / BM, E_), NT, SMEM_B>>>(b1, rw);
    k_gemm2<<<dim3(H_ / BN, T_ / BM), NT, SMEM_B>>>(b2, rw, out);
}

// round 13
// speedup vs baseline: 1.0601x; 1.0601x over previous
#include <cuda_runtime.h>
#include <cuda_fp16.h>
#include <cstdint>

#define E_  8
#define T_  2048
#define H_  2880
#define D_  2880
#define N2_ 5760

__device__ __half g_xh[(size_t)T_ * H_];
__device__ __half g_w1t[(size_t)E_ * N2_ * H_];
__device__ __half g_w2t[(size_t)E_ * H_ * D_];
__device__ __half g_hidden[(size_t)E_ * T_ * D_];

// ---------------- helpers ----------------
__device__ __forceinline__ unsigned smem_u32(const void* p) {
    return (unsigned)__cvta_generic_to_shared(p);
}
__device__ __forceinline__ void cp16h(__half* s, const __half* g) {
    asm volatile("cp.async.cg.shared.global [%0], [%1], 16;" :: "r"(smem_u32(s)), "l"(g));
}
__device__ __forceinline__ void cp_commit() { asm volatile("cp.async.commit_group;"); }
__device__ __forceinline__ void cp_wait1()  { asm volatile("cp.async.wait_group 1;"); }
__device__ __forceinline__ void cp_wait0()  { asm volatile("cp.async.wait_group 0;"); }

__device__ __forceinline__ void mma16(float* c, const uint32_t* a, const uint32_t* b) {
    asm volatile("mma.sync.aligned.m16n8k16.row.col.f32.f16.f16.f32 "
        "{%0,%1,%2,%3}, {%4,%5,%6,%7}, {%8,%9}, {%0,%1,%2,%3};"
        : "+f"(c[0]), "+f"(c[1]), "+f"(c[2]), "+f"(c[3])
        : "r"(a[0]), "r"(a[1]), "r"(a[2]), "r"(a[3]), "r"(b[0]), "r"(b[1]));
}
__device__ __forceinline__ void ldsm4(uint32_t& r0, uint32_t& r1, uint32_t& r2, uint32_t& r3,
                                      uint32_t addr) {
    asm volatile("ldmatrix.sync.aligned.m8n8.x4.shared.b16 {%0,%1,%2,%3}, [%4];"
        : "=r"(r0), "=r"(r1), "=r"(r2), "=r"(r3) : "r"(addr));
}
__device__ __forceinline__ void ldsm2(uint32_t& r0, uint32_t& r1, uint32_t addr) {
    asm volatile("ldmatrix.sync.aligned.m8n8.x2.shared.b16 {%0,%1}, [%2];"
        : "=r"(r0), "=r"(r1) : "r"(addr));
}

// ---------------- tiling ----------------
constexpr int BM = 128, BN = 160, BK = 64;
constexpr int NT = 256;
constexpr int WN = 40, NF = 5;
constexpr int A_BYTES = BM * 128;
constexpr int B_BYTES = BN * 128;
constexpr int STG_B = A_BYTES + B_BYTES;       // 36864
constexpr int STAGES = 3;
constexpr int SMEM_B = STAGES * STG_B;         // 110592 -> 2 CTAs/SM

template<int ROWS>
__device__ __forceinline__ void load_tile(__half* S, const __half* G, int lda, int tid) {
#pragma unroll
    for (int i = 0; i < ROWS * 8 / NT; i++) {
        int c = tid + i * NT;
        int r = c >> 3, q = c & 7;
        cp16h(S + r * 64 + ((q ^ (r & 7)) << 3), G + (size_t)r * lda + q * 8);
    }
}

__device__ __forceinline__ void offs_A(uint32_t (&aOff)[4], int wm, int lane) {
    const int rr = lane & 7, mm = lane >> 3;
#pragma unroll
    for (int i = 0; i < 4; i++) {
        const int row = wm * 64 + i * 16 + (mm & 1) * 8 + rr;
        aOff[i] = row * 128 + ((((mm >> 1) ^ (row & 7)) & 7) << 4);
    }
}
__device__ __forceinline__ void offs_B(uint32_t (&bOff)[3], int wn, int lane) {
    const int rr = lane & 7, mm = lane >> 3;
#pragma unroll
    for (int jp = 0; jp < 2; jp++) {
        const int row = wn * WN + (jp * 2 + (mm >> 1)) * 8 + rr;
        bOff[jp] = row * 128 + ((((mm & 1) ^ (row & 7)) & 7) << 4);
    }
    {
        const int row = wn * WN + 32 + rr;
        bOff[2] = row * 128 + ((((mm & 1) ^ (row & 7)) & 7) << 4);
    }
}

__device__ __forceinline__ void ldsm_batch(uint32_t sA, uint32_t sB,
                                           const uint32_t (&aOff)[4],
                                           const uint32_t (&bOff)[3],
                                           int ks, uint32_t (&a)[4][4], uint32_t (&b)[NF][2]) {
    const uint32_t kx = ks * 32;
#pragma unroll
    for (int i = 0; i < 4; i++)
        ldsm4(a[i][0], a[i][1], a[i][2], a[i][3], sA + (aOff[i] ^ kx));
    ldsm4(b[0][0], b[0][1], b[1][0], b[1][1], sB + (bOff[0] ^ kx));
    ldsm4(b[2][0], b[2][1], b[3][0], b[3][1], sB + (bOff[1] ^ kx));
    ldsm2(b[4][0], b[4][1], sB + (bOff[2] ^ kx));
}
__device__ __forceinline__ void mma_batch(const uint32_t (&a)[4][4], const uint32_t (&b)[NF][2],
                                          float (&acc)[4][NF][4]) {
#pragma unroll
    for (int i = 0; i < 4; i++)
#pragma unroll
        for (int j = 0; j < NF; j++)
            mma16(acc[i][j], a[i], b[j]);
}

// ================= preprocess =================
__global__ void k_tohalf(const float2* __restrict__ in, __half2* __restrict__ out, size_t n2) {
    size_t i = (size_t)blockIdx.x * blockDim.x + threadIdx.x;
    size_t st = (size_t)gridDim.x * blockDim.x;
    for (; i < n2; i += st) {
        float2 v = in[i];
        out[i] = __floats2half2_rn(v.x, v.y);
    }
}
// [z][R][C] fp32 -> [z][C][R] fp16; 64-row x 32-col tiles, half2 coalesced stores
__global__ void k_transpose_h(const float* __restrict__ in, __half* __restrict__ out, int R, int C) {
    __shared__ float t[64][33];
    const float* iz = in + (size_t)blockIdx.z * R * C;
    __half* oz = out + (size_t)blockIdx.z * R * C;
    const int c0 = blockIdx.x * 32, r0 = blockIdx.y * 64;
    const int tx = threadIdx.x, ty = threadIdx.y;
#pragma unroll
    for (int i = 0; i < 64; i += 8)
        t[ty + i][tx] = iz[(size_t)(r0 + ty + i) * C + c0 + tx];
    __syncthreads();
#pragma unroll
    for (int j = 0; j < 4; j++) {
        const int cc = ty + 8 * j;
        __half2 v = __floats2half2_rn(t[2 * tx][cc], t[2 * tx + 1][cc]);
        *(__half2*)(oz + (size_t)(c0 + cc) * R + r0 + 2 * tx) = v;
    }
}

// ================= GEMM1 (exact R9 schedule) =================
__global__ void __launch_bounds__(NT, 2)
k_gemm1(const float* __restrict__ b1, const float* __restrict__ routing) {
    extern __shared__ __align__(128) char smc[];
    __half* smh = (__half*)smc;
    float* smf = (float*)smc;
    const int tid = threadIdx.x, lane = tid & 31, warp = tid >> 5;
    const int wm = warp & 1, wn = warp >> 1;
    const int n0 = blockIdx.x * BN;
    const int t0 = blockIdx.y * BM;
    const int e  = blockIdx.z;

    const uint32_t sb = smem_u32(smc);
    const __half* Ag = g_xh + (size_t)t0 * H_;
    const __half* Bg = g_w1t + ((size_t)e * N2_ + n0) * H_;

    uint32_t aOff[4], bOff[3];
    offs_A(aOff, wm, lane);
    offs_B(bOff, wn, lane);

    float acc[4][NF][4];
#pragma unroll
    for (int i = 0; i < 4; i++)
#pragma unroll
        for (int j = 0; j < NF; j++)
#pragma unroll
            for (int q = 0; q < 4; q++) acc[i][j][q] = 0.f;

    constexpr int KT = H_ / BK;   // 45
#pragma unroll
    for (int s = 0; s < 2; s++) {
        load_tile<BM>(smh + s * STG_B / 2, Ag + s * BK, H_, tid);
        load_tile<BN>(smh + (s * STG_B + A_BYTES) / 2, Bg + s * BK, H_, tid);
        cp_commit();
    }

    for (int kt = 0; kt < KT; kt++) {
        if (kt < KT - 1) cp_wait1(); else cp_wait0();
        __syncthreads();
        const int nk = kt + 2;
        if (nk < KT) {
            const int ns = nk % 3;
            load_tile<BM>(smh + ns * STG_B / 2, Ag + nk * BK, H_, tid);
            load_tile<BN>(smh + (ns * STG_B + A_BYTES) / 2, Bg + nk * BK, H_, tid);
            cp_commit();
        }
        const int s = kt % 3;
        const uint32_t sA = sb + s * STG_B, sB = sA + A_BYTES;
        uint32_t a[4][4], b[NF][2];
#pragma unroll
        for (int ks = 0; ks < 4; ks++) {
            ldsm_batch(sA, sB, aOff, bOff, ks, a, b);
            mma_batch(a, b, acc);
        }
    }

    __syncthreads();
    if (tid < BN) smf[tid] = b1[(size_t)e * N2_ + n0 + tid];
    __syncthreads();

    const int ra = lane >> 2, ca2 = 2 * (lane & 3);
#pragma unroll
    for (int i = 0; i < 4; i++)
#pragma unroll
        for (int h = 0; h < 2; h++) {
            const int row = wm * 64 + i * 16 + h * 8 + ra;
            const float rw = routing[(size_t)(t0 + row) * E_ + e];
            __half* gh = g_hidden + ((size_t)e * T_ + t0 + row) * D_ + (n0 >> 1);
#pragma unroll
            for (int j = 0; j < NF; j++) {
                const int C = wn * WN + j * 8 + ca2;
                float gate = acc[i][j][2 * h]     + smf[C];
                float up   = acc[i][j][2 * h + 1] + smf[C + 1];
                gate = fminf(gate, 7.0f);
                up   = fminf(fmaxf(up, -7.0f), 7.0f);
                const float glu = gate / (1.0f + __expf(-1.702f * gate));
                gh[C >> 1] = __float2half_rn((up + 1.0f) * glu * rw);
            }
        }
}

// ================= GEMM2 (exact R9 schedule) =================
__global__ void __launch_bounds__(NT, 2)
k_gemm2(const float* __restrict__ b2, const float* __restrict__ routing,
        float* __restrict__ out) {
    extern __shared__ __align__(128) char smc[];
    __half* smh = (__half*)smc;
    float* smf = (float*)smc;
    const int tid = threadIdx.x, lane = tid & 31, warp = tid >> 5;
    const int wm = warp & 1, wn = warp >> 1;
    const int h0 = blockIdx.x * BN;
    const int t0 = blockIdx.y * BM;

    const uint32_t sb = smem_u32(smc);
    uint32_t aOff[4], bOff[3];
    offs_A(aOff, wm, lane);
    offs_B(bOff, wn, lane);

    float acc[4][NF][4];
#pragma unroll
    for (int i = 0; i < 4; i++)
#pragma unroll
        for (int j = 0; j < NF; j++)
#pragma unroll
            for (int q = 0; q < 4; q++) acc[i][j][q] = 0.f;

    constexpr int KPE = D_ / BK;   // 45
    constexpr int KT  = E_ * KPE;  // 360

#pragma unroll
    for (int s = 0; s < 2; s++) {
        load_tile<BM>(smh + s * STG_B / 2, g_hidden + (size_t)t0 * D_ + s * BK, D_, tid);
        load_tile<BN>(smh + (s * STG_B + A_BYTES) / 2, g_w2t + (size_t)h0 * D_ + s * BK, D_, tid);
        cp_commit();
    }

    int ez = 0, kk = 2;
    for (int kt = 0; kt < KT; kt++) {
        if (kt < KT - 1) cp_wait1(); else cp_wait0();
        __syncthreads();
        const int nk = kt + 2;
        if (nk < KT) {
            const int ns = nk % 3;
            load_tile<BM>(smh + ns * STG_B / 2,
                          g_hidden + ((size_t)ez * T_ + t0) * D_ + kk * BK, D_, tid);
            load_tile<BN>(smh + (ns * STG_B + A_BYTES) / 2,
                          g_w2t + ((size_t)ez * H_ + h0) * D_ + kk * BK, D_, tid);
            cp_commit();
            if (++kk == KPE) { kk = 0; ez++; }
        }
        const int s = kt % 3;
        const uint32_t sA = sb + s * STG_B, sB = sA + A_BYTES;
        uint32_t a[4][4], b[NF][2];
#pragma unroll
        for (int ks = 0; ks < 4; ks++) {
            ldsm_batch(sA, sB, aOff, bOff, ks, a, b);
            mma_batch(a, b, acc);
        }
    }

    __syncthreads();
    for (int i = tid; i < E_ * BN; i += NT) {
        const int ee = i / BN, c = i - ee * BN;
        smf[i] = b2[(size_t)ee * H_ + h0 + c];
    }
    __syncthreads();

    const int ra = lane >> 2, ca2 = 2 * (lane & 3);
#pragma unroll
    for (int i = 0; i < 4; i++)
#pragma unroll
        for (int h = 0; h < 2; h++) {
            const int t = t0 + wm * 64 + i * 16 + h * 8 + ra;
            const float4 r03 = ((const float4*)routing)[(size_t)t * 2];
            const float4 r47 = ((const float4*)routing)[(size_t)t * 2 + 1];
            const float rwv[8] = { r03.x, r03.y, r03.z, r03.w, r47.x, r47.y, r47.z, r47.w };
            float* orow = out + (size_t)t * H_ + h0;
#pragma unroll
            for (int j = 0; j < NF; j++) {
                const int C = wn * WN + j * 8 + ca2;
                float v0 = acc[i][j][2 * h];
                float v1 = acc[i][j][2 * h + 1];
#pragma unroll
                for (int ee = 0; ee < E_; ee++) {
                    v0 += rwv[ee] * smf[ee * BN + C];
                    v1 += rwv[ee] * smf[ee * BN + C + 1];
                }
                *(float2*)(orow + C) = make_float2(v0, v1);
            }
        }
}

// ================= host ====================
extern "C" void kernel_launch(void* const* d_in, const int* in_sizes, int n_in,
                              void* d_out, int out_size) {
    const float *x = nullptr, *rw = nullptr, *w1 = nullptr, *b1 = nullptr,
                *w2 = nullptr, *b2 = nullptr;
    for (int i = 0; i < n_in; i++) {
        const long long s = in_sizes[i];
        const float* p = (const float*)d_in[i];
        if      (s == (long long)T_ * H_)        x  = p;
        else if (s == (long long)T_ * E_)        rw = p;
        else if (s == (long long)E_ * H_ * N2_)  w1 = p;
        else if (s == (long long)E_ * N2_)       b1 = p;
        else if (s == (long long)E_ * D_ * H_)   w2 = p;
        else if (s == (long long)E_ * H_)        b2 = p;
    }
    float* out = (float*)d_out;

    void *p_xh, *p_w1t, *p_w2t;
    cudaGetSymbolAddress(&p_xh,  g_xh);
    cudaGetSymbolAddress(&p_w1t, g_w1t);
    cudaGetSymbolAddress(&p_w2t, g_w2t);

    cudaFuncSetAttribute(k_gemm1, cudaFuncAttributeMaxDynamicSharedMemorySize, SMEM_B);
    cudaFuncSetAttribute(k_gemm2, cudaFuncAttributeMaxDynamicSharedMemorySize, SMEM_B);

    k_tohalf<<<4096, 256>>>((const float2*)x, (__half2*)p_xh, (size_t)T_ * H_ / 2);
    dim3 tb(32, 8);
    k_transpose_h<<<dim3(N2_ / 32, H_ / 64, E_), tb>>>(w1, (__half*)p_w1t, H_, N2_);
    k_transpose_h<<<dim3(H_ / 32, D_ / 64, E_), tb>>>(w2, (__half*)p_w2t, D_, H_);

    k_gemm1<<<dim3(N2_ / BN, T_ / BM, E_), NT, SMEM_B>>>(b1, rw);
    k_gemm2<<<dim3(H_ / BN, T_ / BM), NT, SMEM_B>>>(b2, rw, out);
}